// round 3
// baseline (speedup 1.0000x reference)
#include <cuda_runtime.h>
#include <cstdint>

// Fused CosFace margin + scale:
// out[r, c] = (logits[r, c] - (c == labels[r] ? M : 0)) * S
// logits: [4096, 50257] fp32 ; labels: [4096] int32 ; out: fp32.
// labels[r] == -1 (invalid) never equals a column index, so no validity check needed.

static constexpr float S = 64.0f;
static constexpr float M = 0.35f;
static constexpr unsigned NC = 50257u;

__global__ void cosface_fused_kernel(const float4* __restrict__ in,
                                     float4* __restrict__ out,
                                     const int* __restrict__ labels,
                                     unsigned n4) {
    unsigned i = blockIdx.x * blockDim.x + threadIdx.x;
    if (i >= n4) return;

    float4 v = in[i];

    unsigned e0 = i * 4u;            // first element index (< 2^31)
    unsigned row = e0 / NC;          // umulhi by magic constant
    unsigned col = e0 - row * NC;

    if (col <= NC - 4u) {
        // All 4 elements in the same row (common case).
        int lbl = __ldg(&labels[row]);
        unsigned d = (unsigned)lbl - col;   // wraps to huge if lbl < col or lbl == -1
        if (d < 4u) {
            float* p = &v.x;
            p[d] -= M;
        }
    } else {
        // Straddles a row boundary (rare: ~3 float4s per boundary).
        float* p = &v.x;
        unsigned r = row, c = col;
        #pragma unroll
        for (int k = 0; k < 4; k++) {
            if (c == NC) { c = 0u; r += 1u; }
            int lbl = __ldg(&labels[r]);
            if ((unsigned)lbl == c) p[k] -= M;
            c += 1u;
        }
    }

    v.x *= S; v.y *= S; v.z *= S; v.w *= S;
    out[i] = v;
}

extern "C" void kernel_launch(void* const* d_in, const int* in_sizes, int n_in,
                              void* d_out, int out_size) {
    const float* logits = (const float*)d_in[0];
    const int* labels = (const int*)d_in[1];
    float* out = (float*)d_out;

    unsigned total = (unsigned)in_sizes[0];   // 4096 * 50257, divisible by 4
    unsigned n4 = total / 4u;

    const int threads = 256;
    unsigned blocks = (n4 + threads - 1) / threads;
    cosface_fused_kernel<<<blocks, threads>>>(
        (const float4*)logits, (float4*)out, labels, n4);
}

// round 4
// speedup vs baseline: 1.0306x; 1.0306x over previous
#include <cuda_runtime.h>
#include <cstdint>

// Fused CosFace margin + scale, 2x float4 per thread, streaming cache hints.
// out[r, c] = (logits[r, c] - (c == labels[r] ? M : 0)) * S
// logits: [4096, 50257] fp32 ; labels: [4096] int32 ; out: fp32.
// labels[r] == -1 never equals a column index, so no validity check needed.

static constexpr float S = 64.0f;
static constexpr float M = 0.35f;
static constexpr unsigned NC = 50257u;

__device__ __forceinline__ void apply_margin(float4& v, unsigned row, unsigned col,
                                             const int* __restrict__ labels) {
    if (col <= NC - 4u) {
        // All 4 elements in the same row (common case).
        unsigned d = (unsigned)__ldg(&labels[row]) - col;  // wraps huge if no match
        if (d < 4u) (&v.x)[d] -= M;
    } else {
        // Straddles a row boundary (rare: ~3 float4s per 50257 elements).
        float* p = &v.x;
        unsigned r = row, c = col;
        #pragma unroll
        for (int k = 0; k < 4; k++) {
            if (c == NC) { c = 0u; r += 1u; }
            if ((unsigned)__ldg(&labels[r]) == c) p[k] -= M;
            c += 1u;
        }
    }
}

__global__ void cosface_fused2_kernel(const float4* __restrict__ in,
                                      float4* __restrict__ out,
                                      const int* __restrict__ labels,
                                      unsigned n4) {
    const unsigned tpb = blockDim.x;                 // 256
    unsigned i0 = blockIdx.x * (tpb * 2u) + threadIdx.x;
    unsigned i1 = i0 + tpb;

    float4 v0, v1;
    bool has0 = i0 < n4, has1 = i1 < n4;
    if (has0) v0 = __ldcs(&in[i0]);
    if (has1) v1 = __ldcs(&in[i1]);

    if (has0) {
        unsigned e0 = i0 * 4u;
        unsigned row0 = e0 / NC;                     // umulhi magic div
        unsigned col0 = e0 - row0 * NC;
        apply_margin(v0, row0, col0, labels);

        if (has1) {
            // Second chunk is exactly 1024 elements later; wraps at most one row.
            unsigned row1 = row0, col1 = col0 + tpb * 4u;
            if (col1 >= NC) { col1 -= NC; row1 += 1u; }
            apply_margin(v1, row1, col1, labels);
        }
    }

    if (has0) {
        v0.x *= S; v0.y *= S; v0.z *= S; v0.w *= S;
        __stcs(&out[i0], v0);
    }
    if (has1) {
        v1.x *= S; v1.y *= S; v1.z *= S; v1.w *= S;
        __stcs(&out[i1], v1);
    }
}

extern "C" void kernel_launch(void* const* d_in, const int* in_sizes, int n_in,
                              void* d_out, int out_size) {
    const float* logits = (const float*)d_in[0];
    const int* labels = (const int*)d_in[1];
    float* out = (float*)d_out;

    unsigned total = (unsigned)in_sizes[0];   // 4096 * 50257, divisible by 4
    unsigned n4 = total / 4u;

    const unsigned threads = 256;
    unsigned per_block = threads * 2u;
    unsigned blocks = (n4 + per_block - 1u) / per_block;
    cosface_fused2_kernel<<<blocks, threads>>>(
        (const float4*)logits, (float4*)out, labels, n4);
}